// round 5
// baseline (speedup 1.0000x reference)
#include <cuda_runtime.h>
#include <cuda_bf16.h>
#include <math.h>
#include <stdint.h>

// Problem constants
#define NB 16384
#define ND 1024
#define NE 8
#define NH 512
#define NT 256
#define NTASK 3

// GEMM tiling (bf16 mma.sync m16n8k16)
#define TM 256
#define TN 128
#define BK 64
#define NSTAGE 3
#define STAGE_A 32768                 // 256 rows x 128 B
#define STAGE_B 16384                 // 128 rows x 128 B
#define OFF_B (NSTAGE * STAGE_A)      // 98304
#define OFF_BIAS (OFF_B + NSTAGE * STAGE_B)  // 147456
#define SMEM_BYTES (OFF_BIAS + 512)

// ---------------------------------------------------------------------------
// Scratch (device globals; no runtime allocation allowed)
// ---------------------------------------------------------------------------
__device__ __nv_bfloat16 g_xb[(size_t)NB * ND];            // x in bf16
__device__ __nv_bfloat16 g_h1b[(size_t)NE * NB * NH];      // [E,B,H] bf16
__device__ __nv_bfloat16 g_eob[(size_t)NE * NB * NH];      // [E,B,H] bf16
__device__ __nv_bfloat16 g_tinb[(size_t)NTASK * NB * NH];  // [T,B,H] bf16
__device__ float g_th[(size_t)NTASK * NB * NT];            // [T,B,T] fp32
__device__ float g_gates[(size_t)NTASK * NB * NE];         // [T,B,E]
__device__ float g_WgT[(size_t)NTASK * NE * ND];           // [T,E,D]
__device__ __nv_bfloat16 g_We1T[(size_t)NE * NH * ND];     // [E,H,D] bf16 NK
__device__ __nv_bfloat16 g_We2T[(size_t)NE * NH * NH];     // [E,H,H]
__device__ __nv_bfloat16 g_Wt1T[(size_t)NTASK * NT * NH];  // [T,NT,H]

// ---------------------------------------------------------------------------
// Helpers (sm_80-class PTX only)
// ---------------------------------------------------------------------------
__device__ __forceinline__ uint32_t smem_u32(const void* p) {
    uint32_t a;
    asm("{ .reg .u64 t; cvta.to.shared.u64 t, %1; cvt.u32.u64 %0, t; }" : "=r"(a) : "l"(p));
    return a;
}

#define CP_ASYNC16(dst, src) \
    asm volatile("cp.async.cg.shared.global [%0], [%1], 16;" :: "r"(dst), "l"(src))
#define CP_COMMIT() asm volatile("cp.async.commit_group;" ::: "memory")
#define CP_WAIT1()  asm volatile("cp.async.wait_group 1;" ::: "memory")
#define CP_WAIT0()  asm volatile("cp.async.wait_group 0;" ::: "memory")

__device__ __forceinline__ void ldmatrix_x4(uint32_t& r0, uint32_t& r1,
                                            uint32_t& r2, uint32_t& r3, uint32_t addr) {
    asm volatile("ldmatrix.sync.aligned.m8n8.x4.shared.b16 {%0,%1,%2,%3}, [%4];"
                 : "=r"(r0), "=r"(r1), "=r"(r2), "=r"(r3) : "r"(addr));
}

__device__ __forceinline__ void mma_bf16(float (&d)[4], const uint32_t (&a)[4],
                                         const uint32_t (&b)[2]) {
    asm volatile(
        "mma.sync.aligned.m16n8k16.row.col.f32.bf16.bf16.f32 "
        "{%0,%1,%2,%3}, {%4,%5,%6,%7}, {%8,%9}, {%0,%1,%2,%3};"
        : "+f"(d[0]), "+f"(d[1]), "+f"(d[2]), "+f"(d[3])
        : "r"(a[0]), "r"(a[1]), "r"(a[2]), "r"(a[3]), "r"(b[0]), "r"(b[1]));
}

__device__ __forceinline__ uint32_t sw128(uint32_t off) {
    return off ^ ((off >> 3) & 0x70);
}

// ---------------------------------------------------------------------------
// fp32 -> bf16 convert (x)
// ---------------------------------------------------------------------------
__global__ __launch_bounds__(256)
void f2b_kernel(const float* __restrict__ in, __nv_bfloat16* __restrict__ out, int n4)
{
    const int i = blockIdx.x * 256 + threadIdx.x;
    if (i >= n4) return;
    float4 v = ((const float4*)in)[i];
    __nv_bfloat162* o = (__nv_bfloat162*)out + i * 2;
    o[0] = __floats2bfloat162_rn(v.x, v.y);
    o[1] = __floats2bfloat162_rn(v.z, v.w);
}

// ---------------------------------------------------------------------------
// Weight transpose + bf16 convert: in fp32 [z][K][N] -> out bf16 [z][N][K]
// ---------------------------------------------------------------------------
__global__ __launch_bounds__(256)
void transpose_bf16_kernel(const float* __restrict__ in, __nv_bfloat16* __restrict__ out,
                           int K, int N)
{
    __shared__ float t[32][33];
    const int z = blockIdx.z;
    in  += (size_t)z * K * N;
    out += (size_t)z * K * N;
    const int k0 = blockIdx.y * 32, n0 = blockIdx.x * 32;
    const int tx = threadIdx.x & 31, ty = threadIdx.x >> 5;  // 32 x 8
#pragma unroll
    for (int i = 0; i < 32; i += 8)
        t[ty + i][tx] = in[(size_t)(k0 + ty + i) * N + n0 + tx];
    __syncthreads();
#pragma unroll
    for (int i = 0; i < 32; i += 8)
        out[(size_t)(n0 + ty + i) * K + k0 + tx] = __float2bfloat16_rn(t[tx][ty + i]);
}

// ---------------------------------------------------------------------------
// Wg transpose: [T,D,E] -> [T,E,D] fp32 (small)
// ---------------------------------------------------------------------------
__global__ __launch_bounds__(256)
void wg_transpose_kernel(const float* __restrict__ Wg, float* __restrict__ WgT)
{
    const int i = blockIdx.x * 256 + threadIdx.x;
    if (i >= NTASK * ND * NE) return;
    const int t = i / (ND * NE);
    const int r = i - t * ND * NE;
    const int d = r >> 3, e = r & 7;
    WgT[((size_t)t * NE + e) * ND + d] = Wg[i];
}

// ---------------------------------------------------------------------------
// bf16 tensor-core batched GEMM: C[z] = relu(A[z] @ Bt[z]^T + bias[z])
//   A : bf16 [M, K] row-major; Bt: bf16 [N, K] row-major
// CTA tile 256x128, BK=64, 3-stage cp.async, 8 warps (4M x 2N),
// warp tile 64x64, m16n8k16 atoms via ldmatrix.x4.
// ---------------------------------------------------------------------------
template <typename OutT>
__global__ __launch_bounds__(256, 1)
void gemm_bf16_kernel(const __nv_bfloat16* __restrict__ Ab,
                      const __nv_bfloat16* __restrict__ Bb,
                      const float* __restrict__ biasb, OutT* __restrict__ Cb,
                      int K, int ldc,
                      long long sA, long long sB, long long sBias, long long sC)
{
    extern __shared__ char dynsmem[];
    const uint32_t smb = smem_u32(dynsmem);

    const int z = blockIdx.z;
    const __nv_bfloat16* A  = Ab + (size_t)z * sA + (size_t)(blockIdx.y * TM) * K;
    const __nv_bfloat16* Bt = Bb + (size_t)z * sB + (size_t)(blockIdx.x * TN) * K;
    const float* bias = biasb + (size_t)z * sBias + blockIdx.x * TN;
    OutT* C = Cb + (size_t)z * sC + (size_t)(blockIdx.y * TM) * ldc + blockIdx.x * TN;

    const int tid   = threadIdx.x;
    const int wid   = tid >> 5;
    const int lane  = tid & 31;
    const int gid   = lane >> 2;
    const int tig   = lane & 3;
    const int warpM = wid >> 1;   // 0..3 -> 64-row slab
    const int warpN = wid & 1;    // 0..1 -> 64-col slab

    float* bias_s = (float*)(dynsmem + OFF_BIAS);
    if (tid < TN) bias_s[tid] = bias[tid];

    // stage loader: A 256 rows + B 128 rows, 128B each, swizzled
    auto load_stage = [&](int buf, int k0) {
        const __nv_bfloat16* Ag = A + k0;
        const __nv_bfloat16* Bg = Bt + k0;
#pragma unroll
        for (int i = 0; i < 8; i++) {
            const int idx = tid + i * 256;      // 0..2047
            const int row = idx >> 3;           // 0..255
            const int c8  = idx & 7;
            const uint32_t off = sw128((uint32_t)(row * 128 + c8 * 16));
            CP_ASYNC16(smb + buf * STAGE_A + off, Ag + (size_t)row * K + c8 * 8);
        }
#pragma unroll
        for (int i = 0; i < 4; i++) {
            const int idx = tid + i * 256;      // 0..1023
            const int row = idx >> 3;           // 0..127
            const int c8  = idx & 7;
            const uint32_t off = sw128((uint32_t)(row * 128 + c8 * 16));
            CP_ASYNC16(smb + OFF_B + buf * STAGE_B + off, Bg + (size_t)row * K + c8 * 8);
        }
        CP_COMMIT();
    };

    float acc[4][8][4];
#pragma unroll
    for (int mt = 0; mt < 4; mt++)
#pragma unroll
        for (int nt = 0; nt < 8; nt++)
#pragma unroll
            for (int r = 0; r < 4; r++) acc[mt][nt][r] = 0.f;

    // ldmatrix lane address components
    const int a_row  = warpM * 64 + (lane & 15);                      // + mt*16
    const int a_koff = (lane >> 4) * 16;                              // + kk*32
    const int b_row  = warpN * 64 + (lane & 7) + ((lane >> 4) << 3);  // + pair*16
    const int b_koff = ((lane >> 3) & 1) * 16;                        // + kk*32

    const int ns = K / BK;
    load_stage(0, 0);
    load_stage(1, BK);

    for (int s = 0; s < ns; s++) {
        if (s + 1 < ns) CP_WAIT1(); else CP_WAIT0();
        __syncthreads();

        const int buf = s % NSTAGE;
        const uint32_t sa = smb + buf * STAGE_A;
        const uint32_t sb = smb + OFF_B + buf * STAGE_B;

#pragma unroll
        for (int kk = 0; kk < 4; kk++) {
            uint32_t af[4][4];
#pragma unroll
            for (int mt = 0; mt < 4; mt++) {
                const uint32_t off = (uint32_t)((a_row + mt * 16) * 128 + kk * 32 + a_koff);
                ldmatrix_x4(af[mt][0], af[mt][1], af[mt][2], af[mt][3], sa + sw128(off));
            }
            uint32_t bf[8][2];
#pragma unroll
            for (int pr = 0; pr < 4; pr++) {
                const uint32_t off = (uint32_t)((b_row + pr * 16) * 128 + kk * 32 + b_koff);
                ldmatrix_x4(bf[pr * 2][0], bf[pr * 2][1], bf[pr * 2 + 1][0], bf[pr * 2 + 1][1],
                            sb + sw128(off));
            }
#pragma unroll
            for (int mt = 0; mt < 4; mt++)
#pragma unroll
                for (int nt = 0; nt < 8; nt++)
                    mma_bf16(acc[mt][nt], af[mt], bf[nt]);
        }
        __syncthreads();
        if (s + 2 < ns) load_stage((s + 2) % NSTAGE, (s + 2) * BK);
    }

    // Epilogue: bias + relu
#pragma unroll
    for (int mt = 0; mt < 4; mt++) {
        const int r0 = warpM * 64 + mt * 16 + gid;
#pragma unroll
        for (int nt = 0; nt < 8; nt++) {
            const int c = warpN * 64 + nt * 8 + tig * 2;
            const float2 bv = *(const float2*)(bias_s + c);
            float v0 = fmaxf(acc[mt][nt][0] + bv.x, 0.f);
            float v1 = fmaxf(acc[mt][nt][1] + bv.y, 0.f);
            float v2 = fmaxf(acc[mt][nt][2] + bv.x, 0.f);
            float v3 = fmaxf(acc[mt][nt][3] + bv.y, 0.f);
            if (sizeof(OutT) == 2) {
                *(__nv_bfloat162*)((__nv_bfloat16*)C + (size_t)r0 * ldc + c) =
                    __floats2bfloat162_rn(v0, v1);
                *(__nv_bfloat162*)((__nv_bfloat16*)C + (size_t)(r0 + 8) * ldc + c) =
                    __floats2bfloat162_rn(v2, v3);
            } else {
                *(float2*)((float*)C + (size_t)r0 * ldc + c) = make_float2(v0, v1);
                *(float2*)((float*)C + (size_t)(r0 + 8) * ldc + c) = make_float2(v2, v3);
            }
        }
    }
}

// ---------------------------------------------------------------------------
// Gates: smem-cached WgT [T,E,D]; block = 8 warps x 4 rows = 32 b rows.
// ---------------------------------------------------------------------------
__global__ __launch_bounds__(256)
void gates_kernel(const float* __restrict__ x, const float* __restrict__ WgT,
                  const float* __restrict__ bg, float* __restrict__ gates)
{
    extern __shared__ float wg_s[];   // [24][1024]
    const int tid = threadIdx.x;
    for (int i = tid; i < NTASK * NE * ND / 4; i += 256)
        ((float4*)wg_s)[i] = ((const float4*)WgT)[i];
    __syncthreads();

    const int wid = tid >> 5, lane = tid & 31;
#pragma unroll 1
    for (int rb = 0; rb < 4; rb++) {
        const int b = blockIdx.x * 32 + wid * 4 + rb;
        const float4* xr = (const float4*)(x + (size_t)b * ND);
        float acc[24];
#pragma unroll
        for (int te = 0; te < 24; te++) acc[te] = 0.f;
#pragma unroll
        for (int i = 0; i < 8; i++) {
            const int d4 = lane + 32 * i;
            const float4 xv = xr[d4];
#pragma unroll
            for (int te = 0; te < 24; te++) {
                const float4 wv = ((const float4*)(wg_s + te * ND))[d4];
                acc[te] += xv.x * wv.x + xv.y * wv.y + xv.z * wv.z + xv.w * wv.w;
            }
        }
#pragma unroll
        for (int off = 16; off > 0; off >>= 1)
#pragma unroll
            for (int te = 0; te < 24; te++)
                acc[te] += __shfl_xor_sync(0xffffffffu, acc[te], off);
        if (lane < NTASK) {
            const int t = lane;
            float v[NE];
            float mx = -1e30f;
#pragma unroll
            for (int e = 0; e < NE; e++) {
                v[e] = acc[t * NE + e] + bg[t * NE + e];
                mx = fmaxf(mx, v[e]);
            }
            float s = 0.f;
#pragma unroll
            for (int e = 0; e < NE; e++) { v[e] = expf(v[e] - mx); s += v[e]; }
            const float inv = 1.f / s;
            float* gout = gates + ((size_t)t * NB + b) * NE;
#pragma unroll
            for (int e = 0; e < NE; e++) gout[e] = v[e] * inv;
        }
    }
}

// ---------------------------------------------------------------------------
// Combine: tin[t,b,h] = sum_e gates[t,b,e] * eo[e,b,h]  (bf16 in/out)
// ---------------------------------------------------------------------------
__global__ __launch_bounds__(256)
void combine_kernel(const __nv_bfloat16* __restrict__ eo, const float* __restrict__ gates,
                    __nv_bfloat16* __restrict__ tin)
{
    const int idx = blockIdx.x * 256 + threadIdx.x;   // over B * NH/8
    const int h8 = idx & (NH / 8 - 1);                // 0..63
    const int b  = idx >> 6;
    if (b >= NB) return;

    float g[NTASK][NE];
#pragma unroll
    for (int t = 0; t < NTASK; t++) {
        const float* gp = gates + ((size_t)t * NB + b) * NE;
#pragma unroll
        for (int e = 0; e < NE; e++) g[t][e] = gp[e];
    }

    float o[NTASK][8];
#pragma unroll
    for (int t = 0; t < NTASK; t++)
#pragma unroll
        for (int j = 0; j < 8; j++) o[t][j] = 0.f;

#pragma unroll
    for (int e = 0; e < NE; e++) {
        const __nv_bfloat162* v =
            (const __nv_bfloat162*)(eo + ((size_t)e * NB + b) * NH + h8 * 8);
        float2 f[4];
#pragma unroll
        for (int j = 0; j < 4; j++) f[j] = __bfloat1622float2(v[j]);
#pragma unroll
        for (int t = 0; t < NTASK; t++) {
            const float ge = g[t][e];
#pragma unroll
            for (int j = 0; j < 4; j++) {
                o[t][j * 2 + 0] = fmaf(ge, f[j].x, o[t][j * 2 + 0]);
                o[t][j * 2 + 1] = fmaf(ge, f[j].y, o[t][j * 2 + 1]);
            }
        }
    }
#pragma unroll
    for (int t = 0; t < NTASK; t++) {
        __nv_bfloat162* op = (__nv_bfloat162*)(tin + ((size_t)t * NB + b) * NH + h8 * 8);
#pragma unroll
        for (int j = 0; j < 4; j++)
            op[j] = __floats2bfloat162_rn(o[t][j * 2], o[t][j * 2 + 1]);
    }
}

// ---------------------------------------------------------------------------
// Tower head: pred[t,b] = sigmoid(th[t,b,:] . Wt2[t,:,0] + bt2[t])
// ---------------------------------------------------------------------------
__global__ __launch_bounds__(256)
void tower2_kernel(const float* __restrict__ th, const float* __restrict__ Wt2,
                   const float* __restrict__ bt2, float* __restrict__ out)
{
    const int warp = (blockIdx.x * blockDim.x + threadIdx.x) >> 5;
    const int lane = threadIdx.x & 31;
    if (warp >= NTASK * NB) return;
    const int t = warp / NB;

    const float* row = th + (size_t)warp * NT;
    const float* w   = Wt2 + (size_t)t * NT;
    float acc = 0.f;
#pragma unroll
    for (int d = lane; d < NT; d += 32) acc = fmaf(row[d], w[d], acc);
#pragma unroll
    for (int off = 16; off > 0; off >>= 1)
        acc += __shfl_xor_sync(0xffffffffu, acc, off);
    if (lane == 0) {
        const float zv = acc + bt2[t];
        out[warp] = 1.f / (1.f + expf(-zv));
    }
}

// ---------------------------------------------------------------------------
// Launch
// ---------------------------------------------------------------------------
extern "C" void kernel_launch(void* const* d_in, const int* in_sizes, int n_in,
                              void* d_out, int out_size)
{
    const float* x   = (const float*)d_in[0];
    const float* We1 = (const float*)d_in[1];
    const float* be1 = (const float*)d_in[2];
    const float* We2 = (const float*)d_in[3];
    const float* be2 = (const float*)d_in[4];
    const float* Wg  = (const float*)d_in[5];
    const float* bg  = (const float*)d_in[6];
    const float* Wt1 = (const float*)d_in[7];
    const float* bt1 = (const float*)d_in[8];
    const float* Wt2 = (const float*)d_in[9];
    const float* bt2 = (const float*)d_in[10];
    float* out = (float*)d_out;

    __nv_bfloat16 *xb, *h1b, *eob, *tinb, *We1T, *We2T, *Wt1T;
    float *th, *gates, *WgT;
    cudaGetSymbolAddress((void**)&xb,    g_xb);
    cudaGetSymbolAddress((void**)&h1b,   g_h1b);
    cudaGetSymbolAddress((void**)&eob,   g_eob);
    cudaGetSymbolAddress((void**)&tinb,  g_tinb);
    cudaGetSymbolAddress((void**)&th,    g_th);
    cudaGetSymbolAddress((void**)&gates, g_gates);
    cudaGetSymbolAddress((void**)&WgT,   g_WgT);
    cudaGetSymbolAddress((void**)&We1T,  g_We1T);
    cudaGetSymbolAddress((void**)&We2T,  g_We2T);
    cudaGetSymbolAddress((void**)&Wt1T,  g_Wt1T);

    cudaFuncSetAttribute(gemm_bf16_kernel<__nv_bfloat16>,
                         cudaFuncAttributeMaxDynamicSharedMemorySize, SMEM_BYTES);
    cudaFuncSetAttribute(gemm_bf16_kernel<float>,
                         cudaFuncAttributeMaxDynamicSharedMemorySize, SMEM_BYTES);
    cudaFuncSetAttribute(gates_kernel,
                         cudaFuncAttributeMaxDynamicSharedMemorySize, NTASK * NE * ND * 4);

    // Converts / transposes (one-time prep per call)
    f2b_kernel<<<(NB * ND / 4 + 255) / 256, 256>>>(x, xb, NB * ND / 4);
    transpose_bf16_kernel<<<dim3(NH / 32, ND / 32, NE), 256>>>(We1, We1T, ND, NH);
    transpose_bf16_kernel<<<dim3(NH / 32, NH / 32, NE), 256>>>(We2, We2T, NH, NH);
    transpose_bf16_kernel<<<dim3(NT / 32, NH / 32, NTASK), 256>>>(Wt1, Wt1T, NH, NT);
    wg_transpose_kernel<<<(NTASK * ND * NE + 255) / 256, 256>>>(Wg, WgT);

    // Gates (independent of expert path)
    gates_kernel<<<NB / 32, 256, NTASK * NE * ND * 4>>>(x, WgT, bg, gates);

    // Expert layer 1: h1[e] = relu(x @ We1[e] + be1[e])
    gemm_bf16_kernel<__nv_bfloat16><<<dim3(NH / TN, NB / TM, NE), 256, SMEM_BYTES>>>(
        xb, We1T, be1, h1b, ND, NH,
        0LL, (long long)NH * ND, (long long)NH, (long long)NB * NH);

    // Expert layer 2: eo[e] = relu(h1[e] @ We2[e] + be2[e])
    gemm_bf16_kernel<__nv_bfloat16><<<dim3(NH / TN, NB / TM, NE), 256, SMEM_BYTES>>>(
        h1b, We2T, be2, eob, NH, NH,
        (long long)NB * NH, (long long)NH * NH, (long long)NH, (long long)NB * NH);

    // Gated combine
    combine_kernel<<<(NB * (NH / 8)) / 256, 256>>>(eob, gates, tinb);

    // Tower layer 1: th[t] = relu(tin[t] @ Wt1[t] + bt1[t])  (fp32 out)
    gemm_bf16_kernel<float><<<dim3(NT / TN, NB / TM, NTASK), 256, SMEM_BYTES>>>(
        tinb, Wt1T, bt1, th, NH, NT,
        (long long)NB * NH, (long long)NT * NH, (long long)NT, (long long)NB * NT);

    // Tower head + sigmoid
    tower2_kernel<<<(NTASK * NB * 32) / 256, 256>>>(th, Wt2, bt2, out);
}

// round 6
// speedup vs baseline: 1.0879x; 1.0879x over previous
#include <cuda_runtime.h>
#include <cuda_bf16.h>
#include <math.h>
#include <stdint.h>

// Problem constants
#define NB 16384
#define ND 1024
#define NE 8
#define NH 512
#define NT 256
#define NTASK 3

// GEMM tiling (bf16 mma.sync m16n8k16)
#define TM 128
#define TN 128
#define BK 64
#define NSTAGE 3
#define STAGE_BYTES 16384             // 128 rows x 128 B (64 bf16)
#define OFF_B (NSTAGE * STAGE_BYTES)  // 49152
#define OFF_BIAS (2 * NSTAGE * STAGE_BYTES)
#define SMEM_BYTES (OFF_BIAS + 512)   // 98816 -> 2 CTAs/SM

// ---------------------------------------------------------------------------
// Scratch (device globals; no runtime allocation allowed)
// ---------------------------------------------------------------------------
__device__ __nv_bfloat16 g_xb[(size_t)NB * ND];            // x in bf16
__device__ __nv_bfloat16 g_h1b[(size_t)NE * NB * NH];      // [E,B,H] bf16
__device__ __nv_bfloat16 g_eob[(size_t)NE * NB * NH];      // [E,B,H] bf16
__device__ __nv_bfloat16 g_tinb[(size_t)NTASK * NB * NH];  // [T,B,H] bf16
__device__ float g_th[(size_t)NTASK * NB * NT];            // [T,B,T] fp32
__device__ float g_gates[(size_t)NTASK * NB * NE];         // [T,B,E]
__device__ float g_WgT[(size_t)NTASK * NE * ND];           // [T,E,D]
__device__ __nv_bfloat16 g_We1T[(size_t)NE * NH * ND];     // [E,H,D] bf16 NK
__device__ __nv_bfloat16 g_We2T[(size_t)NE * NH * NH];     // [E,H,H]
__device__ __nv_bfloat16 g_Wt1T[(size_t)NTASK * NT * NH];  // [T,NT,H]

// ---------------------------------------------------------------------------
// Helpers (sm_80-class PTX only)
// ---------------------------------------------------------------------------
__device__ __forceinline__ uint32_t smem_u32(const void* p) {
    uint32_t a;
    asm("{ .reg .u64 t; cvta.to.shared.u64 t, %1; cvt.u32.u64 %0, t; }" : "=r"(a) : "l"(p));
    return a;
}

#define CP_ASYNC16(dst, src) \
    asm volatile("cp.async.cg.shared.global [%0], [%1], 16;" :: "r"(dst), "l"(src))
#define CP_COMMIT() asm volatile("cp.async.commit_group;" ::: "memory")
#define CP_WAIT1()  asm volatile("cp.async.wait_group 1;" ::: "memory")
#define CP_WAIT0()  asm volatile("cp.async.wait_group 0;" ::: "memory")

__device__ __forceinline__ void ldmatrix_x4(uint32_t& r0, uint32_t& r1,
                                            uint32_t& r2, uint32_t& r3, uint32_t addr) {
    asm volatile("ldmatrix.sync.aligned.m8n8.x4.shared.b16 {%0,%1,%2,%3}, [%4];"
                 : "=r"(r0), "=r"(r1), "=r"(r2), "=r"(r3) : "r"(addr));
}

__device__ __forceinline__ void mma_bf16(float (&d)[4], const uint32_t (&a)[4],
                                         const uint32_t (&b)[2]) {
    asm volatile(
        "mma.sync.aligned.m16n8k16.row.col.f32.bf16.bf16.f32 "
        "{%0,%1,%2,%3}, {%4,%5,%6,%7}, {%8,%9}, {%0,%1,%2,%3};"
        : "+f"(d[0]), "+f"(d[1]), "+f"(d[2]), "+f"(d[3])
        : "r"(a[0]), "r"(a[1]), "r"(a[2]), "r"(a[3]), "r"(b[0]), "r"(b[1]));
}

__device__ __forceinline__ uint32_t sw128(uint32_t off) {
    return off ^ ((off >> 3) & 0x70);
}

// ---------------------------------------------------------------------------
// fp32 -> bf16 convert (x)
// ---------------------------------------------------------------------------
__global__ __launch_bounds__(256)
void f2b_kernel(const float* __restrict__ in, __nv_bfloat16* __restrict__ out, int n4)
{
    const int i = blockIdx.x * 256 + threadIdx.x;
    if (i >= n4) return;
    float4 v = ((const float4*)in)[i];
    __nv_bfloat162* o = (__nv_bfloat162*)out + i * 2;
    o[0] = __floats2bfloat162_rn(v.x, v.y);
    o[1] = __floats2bfloat162_rn(v.z, v.w);
}

// ---------------------------------------------------------------------------
// Weight transpose + bf16 convert: in fp32 [z][K][N] -> out bf16 [z][N][K]
// ---------------------------------------------------------------------------
__global__ __launch_bounds__(256)
void transpose_bf16_kernel(const float* __restrict__ in, __nv_bfloat16* __restrict__ out,
                           int K, int N)
{
    __shared__ float t[32][33];
    const int z = blockIdx.z;
    in  += (size_t)z * K * N;
    out += (size_t)z * K * N;
    const int k0 = blockIdx.y * 32, n0 = blockIdx.x * 32;
    const int tx = threadIdx.x & 31, ty = threadIdx.x >> 5;  // 32 x 8
#pragma unroll
    for (int i = 0; i < 32; i += 8)
        t[ty + i][tx] = in[(size_t)(k0 + ty + i) * N + n0 + tx];
    __syncthreads();
#pragma unroll
    for (int i = 0; i < 32; i += 8)
        out[(size_t)(n0 + ty + i) * K + k0 + tx] = __float2bfloat16_rn(t[tx][ty + i]);
}

// ---------------------------------------------------------------------------
// Wg transpose: [T,D,E] -> [T,E,D] fp32 (small)
// ---------------------------------------------------------------------------
__global__ __launch_bounds__(256)
void wg_transpose_kernel(const float* __restrict__ Wg, float* __restrict__ WgT)
{
    const int i = blockIdx.x * 256 + threadIdx.x;
    if (i >= NTASK * ND * NE) return;
    const int t = i / (ND * NE);
    const int r = i - t * ND * NE;
    const int d = r >> 3, e = r & 7;
    WgT[((size_t)t * NE + e) * ND + d] = Wg[i];
}

// ---------------------------------------------------------------------------
// bf16 tensor-core batched GEMM: C[z] = relu(A[z] @ Bt[z]^T + bias[z])
//   A : bf16 [M, K] row-major; Bt: bf16 [N, K] row-major
// CTA tile 128x128, BK=64, 3-stage cp.async, 4 warps (2M x 2N),
// warp tile 64x64, m16n8k16 atoms via ldmatrix.x4. 2 CTAs/SM.
// ---------------------------------------------------------------------------
template <typename OutT>
__global__ __launch_bounds__(128, 2)
void gemm_bf16_kernel(const __nv_bfloat16* __restrict__ Ab,
                      const __nv_bfloat16* __restrict__ Bb,
                      const float* __restrict__ biasb, OutT* __restrict__ Cb,
                      int K, int ldc,
                      long long sA, long long sB, long long sBias, long long sC)
{
    extern __shared__ char dynsmem[];
    const uint32_t smb = smem_u32(dynsmem);

    const int z = blockIdx.z;
    const __nv_bfloat16* A  = Ab + (size_t)z * sA + (size_t)(blockIdx.y * TM) * K;
    const __nv_bfloat16* Bt = Bb + (size_t)z * sB + (size_t)(blockIdx.x * TN) * K;
    const float* bias = biasb + (size_t)z * sBias + blockIdx.x * TN;
    OutT* C = Cb + (size_t)z * sC + (size_t)(blockIdx.y * TM) * ldc + blockIdx.x * TN;

    const int tid   = threadIdx.x;
    const int wid   = tid >> 5;
    const int lane  = tid & 31;
    const int gid   = lane >> 2;
    const int tig   = lane & 3;
    const int warpM = wid >> 1;   // 0..1 -> 64-row slab
    const int warpN = wid & 1;    // 0..1 -> 64-col slab

    float* bias_s = (float*)(dynsmem + OFF_BIAS);
    if (tid < TN) bias_s[tid] = bias[tid];

    // stage loader: 128 rows x 128B per operand; 128 threads -> 8 chunks each/op
    auto load_stage = [&](int buf, int k0) {
        const __nv_bfloat16* Ag = A + k0;
        const __nv_bfloat16* Bg = Bt + k0;
#pragma unroll
        for (int i = 0; i < 8; i++) {
            const int idx = tid + i * 128;      // 0..1023
            const int row = idx >> 3;           // 0..127
            const int c8  = idx & 7;
            const uint32_t off = sw128((uint32_t)(row * 128 + c8 * 16));
            CP_ASYNC16(smb + buf * STAGE_BYTES + off, Ag + (size_t)row * K + c8 * 8);
            CP_ASYNC16(smb + OFF_B + buf * STAGE_BYTES + off, Bg + (size_t)row * K + c8 * 8);
        }
        CP_COMMIT();
    };

    float acc[4][8][4];
#pragma unroll
    for (int mt = 0; mt < 4; mt++)
#pragma unroll
        for (int nt = 0; nt < 8; nt++)
#pragma unroll
            for (int r = 0; r < 4; r++) acc[mt][nt][r] = 0.f;

    // ldmatrix lane address components
    const int a_row  = warpM * 64 + (lane & 15);                      // + mt*16
    const int a_koff = (lane >> 4) * 16;                              // + kk*32
    const int b_row  = warpN * 64 + (lane & 7) + ((lane >> 4) << 3);  // + pair*16
    const int b_koff = ((lane >> 3) & 1) * 16;                        // + kk*32

    const int ns = K / BK;
    load_stage(0, 0);
    load_stage(1, BK);

    for (int s = 0; s < ns; s++) {
        if (s + 1 < ns) CP_WAIT1(); else CP_WAIT0();
        __syncthreads();   // single barrier per stage: also fences buffer reuse
                           // (buf (s+2)%3 was last read in iter s-1, before this barrier)

        const int buf = s % NSTAGE;
        const uint32_t sa = smb + buf * STAGE_BYTES;
        const uint32_t sb = smb + OFF_B + buf * STAGE_BYTES;

#pragma unroll
        for (int kk = 0; kk < 4; kk++) {
            uint32_t af[4][4];
#pragma unroll
            for (int mt = 0; mt < 4; mt++) {
                const uint32_t off = (uint32_t)((a_row + mt * 16) * 128 + kk * 32 + a_koff);
                ldmatrix_x4(af[mt][0], af[mt][1], af[mt][2], af[mt][3], sa + sw128(off));
            }
            uint32_t bf[8][2];
#pragma unroll
            for (int pr = 0; pr < 4; pr++) {
                const uint32_t off = (uint32_t)((b_row + pr * 16) * 128 + kk * 32 + b_koff);
                ldmatrix_x4(bf[pr * 2][0], bf[pr * 2][1], bf[pr * 2 + 1][0], bf[pr * 2 + 1][1],
                            sb + sw128(off));
            }
#pragma unroll
            for (int mt = 0; mt < 4; mt++)
#pragma unroll
                for (int nt = 0; nt < 8; nt++)
                    mma_bf16(acc[mt][nt], af[mt], bf[nt]);
        }
        if (s + 2 < ns) load_stage((s + 2) % NSTAGE, (s + 2) * BK);
    }

    // Epilogue: bias + relu
#pragma unroll
    for (int mt = 0; mt < 4; mt++) {
        const int r0 = warpM * 64 + mt * 16 + gid;
#pragma unroll
        for (int nt = 0; nt < 8; nt++) {
            const int c = warpN * 64 + nt * 8 + tig * 2;
            const float2 bv = *(const float2*)(bias_s + c);
            float v0 = fmaxf(acc[mt][nt][0] + bv.x, 0.f);
            float v1 = fmaxf(acc[mt][nt][1] + bv.y, 0.f);
            float v2 = fmaxf(acc[mt][nt][2] + bv.x, 0.f);
            float v3 = fmaxf(acc[mt][nt][3] + bv.y, 0.f);
            if (sizeof(OutT) == 2) {
                *(__nv_bfloat162*)((__nv_bfloat16*)C + (size_t)r0 * ldc + c) =
                    __floats2bfloat162_rn(v0, v1);
                *(__nv_bfloat162*)((__nv_bfloat16*)C + (size_t)(r0 + 8) * ldc + c) =
                    __floats2bfloat162_rn(v2, v3);
            } else {
                *(float2*)((float*)C + (size_t)r0 * ldc + c) = make_float2(v0, v1);
                *(float2*)((float*)C + (size_t)(r0 + 8) * ldc + c) = make_float2(v2, v3);
            }
        }
    }
}

// ---------------------------------------------------------------------------
// Gates: smem-cached WgT [T,E,D]; block = 8 warps x 4 rows = 32 b rows.
// ---------------------------------------------------------------------------
__global__ __launch_bounds__(256)
void gates_kernel(const float* __restrict__ x, const float* __restrict__ WgT,
                  const float* __restrict__ bg, float* __restrict__ gates)
{
    extern __shared__ float wg_s[];   // [24][1024]
    const int tid = threadIdx.x;
    for (int i = tid; i < NTASK * NE * ND / 4; i += 256)
        ((float4*)wg_s)[i] = ((const float4*)WgT)[i];
    __syncthreads();

    const int wid = tid >> 5, lane = tid & 31;
#pragma unroll 1
    for (int rb = 0; rb < 4; rb++) {
        const int b = blockIdx.x * 32 + wid * 4 + rb;
        const float4* xr = (const float4*)(x + (size_t)b * ND);
        float acc[24];
#pragma unroll
        for (int te = 0; te < 24; te++) acc[te] = 0.f;
#pragma unroll
        for (int i = 0; i < 8; i++) {
            const int d4 = lane + 32 * i;
            const float4 xv = xr[d4];
#pragma unroll
            for (int te = 0; te < 24; te++) {
                const float4 wv = ((const float4*)(wg_s + te * ND))[d4];
                acc[te] += xv.x * wv.x + xv.y * wv.y + xv.z * wv.z + xv.w * wv.w;
            }
        }
#pragma unroll
        for (int off = 16; off > 0; off >>= 1)
#pragma unroll
            for (int te = 0; te < 24; te++)
                acc[te] += __shfl_xor_sync(0xffffffffu, acc[te], off);
        if (lane < NTASK) {
            const int t = lane;
            float v[NE];
            float mx = -1e30f;
#pragma unroll
            for (int e = 0; e < NE; e++) {
                v[e] = acc[t * NE + e] + bg[t * NE + e];
                mx = fmaxf(mx, v[e]);
            }
            float s = 0.f;
#pragma unroll
            for (int e = 0; e < NE; e++) { v[e] = expf(v[e] - mx); s += v[e]; }
            const float inv = 1.f / s;
            float* gout = gates + ((size_t)t * NB + b) * NE;
#pragma unroll
            for (int e = 0; e < NE; e++) gout[e] = v[e] * inv;
        }
    }
}

// ---------------------------------------------------------------------------
// Combine: tin[t,b,h] = sum_e gates[t,b,e] * eo[e,b,h]  (bf16 in/out)
// ---------------------------------------------------------------------------
__global__ __launch_bounds__(256)
void combine_kernel(const __nv_bfloat16* __restrict__ eo, const float* __restrict__ gates,
                    __nv_bfloat16* __restrict__ tin)
{
    const int idx = blockIdx.x * 256 + threadIdx.x;   // over B * NH/8
    const int h8 = idx & (NH / 8 - 1);                // 0..63
    const int b  = idx >> 6;
    if (b >= NB) return;

    float g[NTASK][NE];
#pragma unroll
    for (int t = 0; t < NTASK; t++) {
        const float* gp = gates + ((size_t)t * NB + b) * NE;
#pragma unroll
        for (int e = 0; e < NE; e++) g[t][e] = gp[e];
    }

    float o[NTASK][8];
#pragma unroll
    for (int t = 0; t < NTASK; t++)
#pragma unroll
        for (int j = 0; j < 8; j++) o[t][j] = 0.f;

#pragma unroll
    for (int e = 0; e < NE; e++) {
        const __nv_bfloat162* v =
            (const __nv_bfloat162*)(eo + ((size_t)e * NB + b) * NH + h8 * 8);
        float2 f[4];
#pragma unroll
        for (int j = 0; j < 4; j++) f[j] = __bfloat1622float2(v[j]);
#pragma unroll
        for (int t = 0; t < NTASK; t++) {
            const float ge = g[t][e];
#pragma unroll
            for (int j = 0; j < 4; j++) {
                o[t][j * 2 + 0] = fmaf(ge, f[j].x, o[t][j * 2 + 0]);
                o[t][j * 2 + 1] = fmaf(ge, f[j].y, o[t][j * 2 + 1]);
            }
        }
    }
#pragma unroll
    for (int t = 0; t < NTASK; t++) {
        __nv_bfloat162* op = (__nv_bfloat162*)(tin + ((size_t)t * NB + b) * NH + h8 * 8);
#pragma unroll
        for (int j = 0; j < 4; j++)
            op[j] = __floats2bfloat162_rn(o[t][j * 2], o[t][j * 2 + 1]);
    }
}

// ---------------------------------------------------------------------------
// Tower head: pred[t,b] = sigmoid(th[t,b,:] . Wt2[t,:,0] + bt2[t])
// ---------------------------------------------------------------------------
__global__ __launch_bounds__(256)
void tower2_kernel(const float* __restrict__ th, const float* __restrict__ Wt2,
                   const float* __restrict__ bt2, float* __restrict__ out)
{
    const int warp = (blockIdx.x * blockDim.x + threadIdx.x) >> 5;
    const int lane = threadIdx.x & 31;
    if (warp >= NTASK * NB) return;
    const int t = warp / NB;

    const float* row = th + (size_t)warp * NT;
    const float* w   = Wt2 + (size_t)t * NT;
    float acc = 0.f;
#pragma unroll
    for (int d = lane; d < NT; d += 32) acc = fmaf(row[d], w[d], acc);
#pragma unroll
    for (int off = 16; off > 0; off >>= 1)
        acc += __shfl_xor_sync(0xffffffffu, acc, off);
    if (lane == 0) {
        const float zv = acc + bt2[t];
        out[warp] = 1.f / (1.f + expf(-zv));
    }
}

// ---------------------------------------------------------------------------
// Launch
// ---------------------------------------------------------------------------
extern "C" void kernel_launch(void* const* d_in, const int* in_sizes, int n_in,
                              void* d_out, int out_size)
{
    const float* x   = (const float*)d_in[0];
    const float* We1 = (const float*)d_in[1];
    const float* be1 = (const float*)d_in[2];
    const float* We2 = (const float*)d_in[3];
    const float* be2 = (const float*)d_in[4];
    const float* Wg  = (const float*)d_in[5];
    const float* bg  = (const float*)d_in[6];
    const float* Wt1 = (const float*)d_in[7];
    const float* bt1 = (const float*)d_in[8];
    const float* Wt2 = (const float*)d_in[9];
    const float* bt2 = (const float*)d_in[10];
    float* out = (float*)d_out;

    __nv_bfloat16 *xb, *h1b, *eob, *tinb, *We1T, *We2T, *Wt1T;
    float *th, *gates, *WgT;
    cudaGetSymbolAddress((void**)&xb,    g_xb);
    cudaGetSymbolAddress((void**)&h1b,   g_h1b);
    cudaGetSymbolAddress((void**)&eob,   g_eob);
    cudaGetSymbolAddress((void**)&tinb,  g_tinb);
    cudaGetSymbolAddress((void**)&th,    g_th);
    cudaGetSymbolAddress((void**)&gates, g_gates);
    cudaGetSymbolAddress((void**)&WgT,   g_WgT);
    cudaGetSymbolAddress((void**)&We1T,  g_We1T);
    cudaGetSymbolAddress((void**)&We2T,  g_We2T);
    cudaGetSymbolAddress((void**)&Wt1T,  g_Wt1T);

    cudaFuncSetAttribute(gemm_bf16_kernel<__nv_bfloat16>,
                         cudaFuncAttributeMaxDynamicSharedMemorySize, SMEM_BYTES);
    cudaFuncSetAttribute(gemm_bf16_kernel<float>,
                         cudaFuncAttributeMaxDynamicSharedMemorySize, SMEM_BYTES);
    cudaFuncSetAttribute(gates_kernel,
                         cudaFuncAttributeMaxDynamicSharedMemorySize, NTASK * NE * ND * 4);

    // Converts / transposes (one-time prep per call)
    f2b_kernel<<<(NB * ND / 4 + 255) / 256, 256>>>(x, xb, NB * ND / 4);
    transpose_bf16_kernel<<<dim3(NH / 32, ND / 32, NE), 256>>>(We1, We1T, ND, NH);
    transpose_bf16_kernel<<<dim3(NH / 32, NH / 32, NE), 256>>>(We2, We2T, NH, NH);
    transpose_bf16_kernel<<<dim3(NT / 32, NH / 32, NTASK), 256>>>(Wt1, Wt1T, NH, NT);
    wg_transpose_kernel<<<(NTASK * ND * NE + 255) / 256, 256>>>(Wg, WgT);

    // Gates (independent of expert path)
    gates_kernel<<<NB / 32, 256, NTASK * NE * ND * 4>>>(x, WgT, bg, gates);

    // Expert layer 1: h1[e] = relu(x @ We1[e] + be1[e])
    gemm_bf16_kernel<__nv_bfloat16><<<dim3(NH / TN, NB / TM, NE), 128, SMEM_BYTES>>>(
        xb, We1T, be1, h1b, ND, NH,
        0LL, (long long)NH * ND, (long long)NH, (long long)NB * NH);

    // Expert layer 2: eo[e] = relu(h1[e] @ We2[e] + be2[e])
    gemm_bf16_kernel<__nv_bfloat16><<<dim3(NH / TN, NB / TM, NE), 128, SMEM_BYTES>>>(
        h1b, We2T, be2, eob, NH, NH,
        (long long)NB * NH, (long long)NH * NH, (long long)NH, (long long)NB * NH);

    // Gated combine
    combine_kernel<<<(NB * (NH / 8)) / 256, 256>>>(eob, gates, tinb);

    // Tower layer 1: th[t] = relu(tin[t] @ Wt1[t] + bt1[t])  (fp32 out)
    gemm_bf16_kernel<float><<<dim3(NT / TN, NB / TM, NTASK), 128, SMEM_BYTES>>>(
        tinb, Wt1T, bt1, th, NH, NT,
        (long long)NB * NH, (long long)NT * NH, (long long)NT, (long long)NB * NT);

    // Tower head + sigmoid
    tower2_kernel<<<(NTASK * NB * 32) / 256, 256>>>(th, Wt2, bt2, out);
}

// round 7
// speedup vs baseline: 1.0918x; 1.0036x over previous
#include <cuda_runtime.h>
#include <cuda_bf16.h>
#include <math.h>
#include <stdint.h>

// Problem constants
#define NB 16384
#define ND 1024
#define NE 8
#define NH 512
#define NT 256
#define NTASK 3

// GEMM tiling (bf16 mma.sync m16n8k16)
#define TM 128
#define TN 128
#define BK 64
#define NSTAGE 3
#define STAGE_BYTES 16384             // 128 rows x 128 B (64 bf16)
#define OFF_B (NSTAGE * STAGE_BYTES)  // 49152
#define OFF_BIAS (2 * NSTAGE * STAGE_BYTES)
#define SMEM_BYTES (OFF_BIAS + 512)   // 98816 -> 2 CTAs/SM

// Fused gates kernel smem: 24 rows x 1032 floats (pitch pads banks)
#define WG_PITCH 1032
#define GATES_SMEM (NTASK * NE * WG_PITCH * 4)

// ---------------------------------------------------------------------------
// Scratch (device globals; no runtime allocation allowed)
// ---------------------------------------------------------------------------
__device__ __nv_bfloat16 g_xb[(size_t)NB * ND];            // x in bf16
__device__ __nv_bfloat16 g_h1b[(size_t)NE * NB * NH];      // [E,B,H] bf16
__device__ __nv_bfloat16 g_eob[(size_t)NE * NB * NH];      // [E,B,H] bf16
__device__ __nv_bfloat16 g_tinb[(size_t)NTASK * NB * NH];  // [T,B,H] bf16
__device__ float g_th[(size_t)NTASK * NB * NT];            // [T,B,T] fp32
__device__ float g_gates[(size_t)NTASK * NB * NE];         // [T,B,E]
__device__ __nv_bfloat16 g_We1T[(size_t)NE * NH * ND];     // [E,H,D] bf16 NK
__device__ __nv_bfloat16 g_We2T[(size_t)NE * NH * NH];     // [E,H,H]
__device__ __nv_bfloat16 g_Wt1T[(size_t)NTASK * NT * NH];  // [T,NT,H]

// ---------------------------------------------------------------------------
// Helpers (sm_80-class PTX only)
// ---------------------------------------------------------------------------
__device__ __forceinline__ uint32_t smem_u32(const void* p) {
    uint32_t a;
    asm("{ .reg .u64 t; cvta.to.shared.u64 t, %1; cvt.u32.u64 %0, t; }" : "=r"(a) : "l"(p));
    return a;
}

#define CP_ASYNC16(dst, src) \
    asm volatile("cp.async.cg.shared.global [%0], [%1], 16;" :: "r"(dst), "l"(src))
#define CP_COMMIT() asm volatile("cp.async.commit_group;" ::: "memory")
#define CP_WAIT1()  asm volatile("cp.async.wait_group 1;" ::: "memory")
#define CP_WAIT0()  asm volatile("cp.async.wait_group 0;" ::: "memory")

__device__ __forceinline__ void ldmatrix_x4(uint32_t& r0, uint32_t& r1,
                                            uint32_t& r2, uint32_t& r3, uint32_t addr) {
    asm volatile("ldmatrix.sync.aligned.m8n8.x4.shared.b16 {%0,%1,%2,%3}, [%4];"
                 : "=r"(r0), "=r"(r1), "=r"(r2), "=r"(r3) : "r"(addr));
}

__device__ __forceinline__ void mma_bf16(float (&d)[4], const uint32_t (&a)[4],
                                         const uint32_t (&b)[2]) {
    asm volatile(
        "mma.sync.aligned.m16n8k16.row.col.f32.bf16.bf16.f32 "
        "{%0,%1,%2,%3}, {%4,%5,%6,%7}, {%8,%9}, {%0,%1,%2,%3};"
        : "+f"(d[0]), "+f"(d[1]), "+f"(d[2]), "+f"(d[3])
        : "r"(a[0]), "r"(a[1]), "r"(a[2]), "r"(a[3]), "r"(b[0]), "r"(b[1]));
}

__device__ __forceinline__ uint32_t sw128(uint32_t off) {
    return off ^ ((off >> 3) & 0x70);
}

// ---------------------------------------------------------------------------
// Merged weight transpose + bf16 convert: fp32 [z][K][N] -> bf16 [z][N][K]
// One launch covers We1 (4096 tiles), We2 (2048), Wt1 (384).
// ---------------------------------------------------------------------------
__global__ __launch_bounds__(256)
void prep_weights_kernel(const float* __restrict__ We1, __nv_bfloat16* __restrict__ We1T,
                         const float* __restrict__ We2, __nv_bfloat16* __restrict__ We2T,
                         const float* __restrict__ Wt1, __nv_bfloat16* __restrict__ Wt1T)
{
    __shared__ float t[32][33];
    const int bid = blockIdx.x;

    const float* in;
    __nv_bfloat16* out;
    int K, N, z, ky, nx;
    if (bid < 4096) {                    // We1: z=8, K=1024, N=512 -> 32x16 tiles
        const int r = bid;
        z = r >> 9; const int tt = r & 511;
        ky = tt >> 4; nx = tt & 15;
        K = ND; N = NH; in = We1; out = We1T;
    } else if (bid < 6144) {             // We2: z=8, K=512, N=512 -> 16x16 tiles
        const int r = bid - 4096;
        z = r >> 8; const int tt = r & 255;
        ky = tt >> 4; nx = tt & 15;
        K = NH; N = NH; in = We2; out = We2T;
    } else {                             // Wt1: z=3, K=512, N=256 -> 16x8 tiles
        const int r = bid - 6144;
        z = r >> 7; const int tt = r & 127;
        ky = tt >> 3; nx = tt & 7;
        K = NH; N = NT; in = Wt1; out = Wt1T;
    }
    in  += (size_t)z * K * N;
    out += (size_t)z * K * N;
    const int k0 = ky * 32, n0 = nx * 32;
    const int tx = threadIdx.x & 31, ty = threadIdx.x >> 5;  // 32 x 8
#pragma unroll
    for (int i = 0; i < 32; i += 8)
        t[ty + i][tx] = in[(size_t)(k0 + ty + i) * N + n0 + tx];
    __syncthreads();
#pragma unroll
    for (int i = 0; i < 32; i += 8)
        out[(size_t)(n0 + ty + i) * K + k0 + tx] = __float2bfloat16_rn(t[tx][ty + i]);
}

// ---------------------------------------------------------------------------
// Fused input kernel: reads x once per row; writes xb (bf16), computes the 24
// gate logits (softmax over experts per task), writes gates.
// Wg staged into smem directly from native [T,D,E] layout.
// Block: 256 threads, 8 warps x 4 rows = 32 rows; grid NB/32 = 512.
// ---------------------------------------------------------------------------
__global__ __launch_bounds__(256)
void fused_input_kernel(const float* __restrict__ x, const float* __restrict__ Wg,
                        const float* __restrict__ bg,
                        __nv_bfloat16* __restrict__ xb, float* __restrict__ gates)
{
    extern __shared__ float wg_s[];   // [24][WG_PITCH]
    const int tid = threadIdx.x;

    // Stage Wg [T,D,E] -> wg_s[(t*8+e)][d], float4 over e (4 scattered stores)
    for (int i = tid; i < NTASK * ND * NE / 4; i += 256) {
        const float4 v = ((const float4*)Wg)[i];
        const int base = i * 4;                    // element index in [T,D,E]
        const int tt = base / (ND * NE);
        const int r  = base - tt * (ND * NE);
        const int d  = r >> 3;
        const int e0 = r & 7;                      // 0 or 4
        wg_s[(tt * NE + e0 + 0) * WG_PITCH + d] = v.x;
        wg_s[(tt * NE + e0 + 1) * WG_PITCH + d] = v.y;
        wg_s[(tt * NE + e0 + 2) * WG_PITCH + d] = v.z;
        wg_s[(tt * NE + e0 + 3) * WG_PITCH + d] = v.w;
    }
    __syncthreads();

    const int wid = tid >> 5, lane = tid & 31;
#pragma unroll 1
    for (int rb = 0; rb < 4; rb++) {
        const int b = blockIdx.x * 32 + wid * 4 + rb;
        const float4* xr = (const float4*)(x + (size_t)b * ND);
        __nv_bfloat162* xo = (__nv_bfloat162*)(g_xb + (size_t)b * ND);
        float acc[24];
#pragma unroll
        for (int te = 0; te < 24; te++) acc[te] = 0.f;
#pragma unroll
        for (int i = 0; i < 8; i++) {
            const int d4 = lane + 32 * i;
            const float4 xv = xr[d4];
            // convert + store bf16 copy of x
            xo[d4 * 2 + 0] = __floats2bfloat162_rn(xv.x, xv.y);
            xo[d4 * 2 + 1] = __floats2bfloat162_rn(xv.z, xv.w);
#pragma unroll
            for (int te = 0; te < 24; te++) {
                const float* wr = wg_s + te * WG_PITCH + d4 * 4;
                const float4 wv = *(const float4*)wr;
                acc[te] += xv.x * wv.x + xv.y * wv.y + xv.z * wv.z + xv.w * wv.w;
            }
        }
#pragma unroll
        for (int off = 16; off > 0; off >>= 1)
#pragma unroll
            for (int te = 0; te < 24; te++)
                acc[te] += __shfl_xor_sync(0xffffffffu, acc[te], off);
        if (lane < NTASK) {
            const int t = lane;
            float v[NE];
            float mx = -1e30f;
#pragma unroll
            for (int e = 0; e < NE; e++) {
                v[e] = acc[t * NE + e] + bg[t * NE + e];
                mx = fmaxf(mx, v[e]);
            }
            float s = 0.f;
#pragma unroll
            for (int e = 0; e < NE; e++) { v[e] = expf(v[e] - mx); s += v[e]; }
            const float inv = 1.f / s;
            float* gout = gates + ((size_t)t * NB + b) * NE;
#pragma unroll
            for (int e = 0; e < NE; e++) gout[e] = v[e] * inv;
        }
    }
}

// ---------------------------------------------------------------------------
// bf16 tensor-core batched GEMM: C[z] = relu(A[z] @ Bt[z]^T + bias[z])
//   A : bf16 [M, K] row-major; Bt: bf16 [N, K] row-major
// CTA tile 128x128, BK=64, 3-stage cp.async, 4 warps (2M x 2N),
// warp tile 64x64, m16n8k16 atoms via ldmatrix.x4. 2 CTAs/SM.
// ---------------------------------------------------------------------------
template <typename OutT>
__global__ __launch_bounds__(128, 2)
void gemm_bf16_kernel(const __nv_bfloat16* __restrict__ Ab,
                      const __nv_bfloat16* __restrict__ Bb,
                      const float* __restrict__ biasb, OutT* __restrict__ Cb,
                      int K, int ldc,
                      long long sA, long long sB, long long sBias, long long sC)
{
    extern __shared__ char dynsmem[];
    const uint32_t smb = smem_u32(dynsmem);

    const int z = blockIdx.z;
    const __nv_bfloat16* A  = Ab + (size_t)z * sA + (size_t)(blockIdx.y * TM) * K;
    const __nv_bfloat16* Bt = Bb + (size_t)z * sB + (size_t)(blockIdx.x * TN) * K;
    const float* bias = biasb + (size_t)z * sBias + blockIdx.x * TN;
    OutT* C = Cb + (size_t)z * sC + (size_t)(blockIdx.y * TM) * ldc + blockIdx.x * TN;

    const int tid   = threadIdx.x;
    const int wid   = tid >> 5;
    const int lane  = tid & 31;
    const int gid   = lane >> 2;
    const int tig   = lane & 3;
    const int warpM = wid >> 1;   // 0..1 -> 64-row slab
    const int warpN = wid & 1;    // 0..1 -> 64-col slab

    float* bias_s = (float*)(dynsmem + OFF_BIAS);
    if (tid < TN) bias_s[tid] = bias[tid];

    // stage loader: 128 rows x 128B per operand; 128 threads -> 8 chunks each/op
    auto load_stage = [&](int buf, int k0) {
        const __nv_bfloat16* Ag = A + k0;
        const __nv_bfloat16* Bg = Bt + k0;
#pragma unroll
        for (int i = 0; i < 8; i++) {
            const int idx = tid + i * 128;      // 0..1023
            const int row = idx >> 3;           // 0..127
            const int c8  = idx & 7;
            const uint32_t off = sw128((uint32_t)(row * 128 + c8 * 16));
            CP_ASYNC16(smb + buf * STAGE_BYTES + off, Ag + (size_t)row * K + c8 * 8);
            CP_ASYNC16(smb + OFF_B + buf * STAGE_BYTES + off, Bg + (size_t)row * K + c8 * 8);
        }
        CP_COMMIT();
    };

    float acc[4][8][4];
#pragma unroll
    for (int mt = 0; mt < 4; mt++)
#pragma unroll
        for (int nt = 0; nt < 8; nt++)
#pragma unroll
            for (int r = 0; r < 4; r++) acc[mt][nt][r] = 0.f;

    // ldmatrix lane address components
    const int a_row  = warpM * 64 + (lane & 15);                      // + mt*16
    const int a_koff = (lane >> 4) * 16;                              // + kk*32
    const int b_row  = warpN * 64 + (lane & 7) + ((lane >> 4) << 3);  // + pair*16
    const int b_koff = ((lane >> 3) & 1) * 16;                        // + kk*32

    const int ns = K / BK;
    load_stage(0, 0);
    load_stage(1, BK);

    for (int s = 0; s < ns; s++) {
        if (s + 1 < ns) CP_WAIT1(); else CP_WAIT0();
        __syncthreads();   // single barrier per stage: also fences buffer reuse

        const int buf = s % NSTAGE;
        const uint32_t sa = smb + buf * STAGE_BYTES;
        const uint32_t sb = smb + OFF_B + buf * STAGE_BYTES;

#pragma unroll
        for (int kk = 0; kk < 4; kk++) {
            uint32_t af[4][4];
#pragma unroll
            for (int mt = 0; mt < 4; mt++) {
                const uint32_t off = (uint32_t)((a_row + mt * 16) * 128 + kk * 32 + a_koff);
                ldmatrix_x4(af[mt][0], af[mt][1], af[mt][2], af[mt][3], sa + sw128(off));
            }
            uint32_t bf[8][2];
#pragma unroll
            for (int pr = 0; pr < 4; pr++) {
                const uint32_t off = (uint32_t)((b_row + pr * 16) * 128 + kk * 32 + b_koff);
                ldmatrix_x4(bf[pr * 2][0], bf[pr * 2][1], bf[pr * 2 + 1][0], bf[pr * 2 + 1][1],
                            sb + sw128(off));
            }
#pragma unroll
            for (int mt = 0; mt < 4; mt++)
#pragma unroll
                for (int nt = 0; nt < 8; nt++)
                    mma_bf16(acc[mt][nt], af[mt], bf[nt]);
        }
        if (s + 2 < ns) load_stage((s + 2) % NSTAGE, (s + 2) * BK);
    }

    // Epilogue: bias + relu
#pragma unroll
    for (int mt = 0; mt < 4; mt++) {
        const int r0 = warpM * 64 + mt * 16 + gid;
#pragma unroll
        for (int nt = 0; nt < 8; nt++) {
            const int c = warpN * 64 + nt * 8 + tig * 2;
            const float2 bv = *(const float2*)(bias_s + c);
            float v0 = fmaxf(acc[mt][nt][0] + bv.x, 0.f);
            float v1 = fmaxf(acc[mt][nt][1] + bv.y, 0.f);
            float v2 = fmaxf(acc[mt][nt][2] + bv.x, 0.f);
            float v3 = fmaxf(acc[mt][nt][3] + bv.y, 0.f);
            if (sizeof(OutT) == 2) {
                *(__nv_bfloat162*)((__nv_bfloat16*)C + (size_t)r0 * ldc + c) =
                    __floats2bfloat162_rn(v0, v1);
                *(__nv_bfloat162*)((__nv_bfloat16*)C + (size_t)(r0 + 8) * ldc + c) =
                    __floats2bfloat162_rn(v2, v3);
            } else {
                *(float2*)((float*)C + (size_t)r0 * ldc + c) = make_float2(v0, v1);
                *(float2*)((float*)C + (size_t)(r0 + 8) * ldc + c) = make_float2(v2, v3);
            }
        }
    }
}

// ---------------------------------------------------------------------------
// Combine: tin[t,b,h] = sum_e gates[t,b,e] * eo[e,b,h]  (bf16 in/out)
// ---------------------------------------------------------------------------
__global__ __launch_bounds__(256)
void combine_kernel(const __nv_bfloat16* __restrict__ eo, const float* __restrict__ gates,
                    __nv_bfloat16* __restrict__ tin)
{
    const int idx = blockIdx.x * 256 + threadIdx.x;   // over B * NH/8
    const int h8 = idx & (NH / 8 - 1);                // 0..63
    const int b  = idx >> 6;
    if (b >= NB) return;

    float g[NTASK][NE];
#pragma unroll
    for (int t = 0; t < NTASK; t++) {
        const float* gp = gates + ((size_t)t * NB + b) * NE;
#pragma unroll
        for (int e = 0; e < NE; e++) g[t][e] = gp[e];
    }

    float o[NTASK][8];
#pragma unroll
    for (int t = 0; t < NTASK; t++)
#pragma unroll
        for (int j = 0; j < 8; j++) o[t][j] = 0.f;

#pragma unroll
    for (int e = 0; e < NE; e++) {
        const __nv_bfloat162* v =
            (const __nv_bfloat162*)(eo + ((size_t)e * NB + b) * NH + h8 * 8);
        float2 f[4];
#pragma unroll
        for (int j = 0; j < 4; j++) f[j] = __bfloat1622float2(v[j]);
#pragma unroll
        for (int t = 0; t < NTASK; t++) {
            const float ge = g[t][e];
#pragma unroll
            for (int j = 0; j < 4; j++) {
                o[t][j * 2 + 0] = fmaf(ge, f[j].x, o[t][j * 2 + 0]);
                o[t][j * 2 + 1] = fmaf(ge, f[j].y, o[t][j * 2 + 1]);
            }
        }
    }
#pragma unroll
    for (int t = 0; t < NTASK; t++) {
        __nv_bfloat162* op = (__nv_bfloat162*)(tin + ((size_t)t * NB + b) * NH + h8 * 8);
#pragma unroll
        for (int j = 0; j < 4; j++)
            op[j] = __floats2bfloat162_rn(o[t][j * 2], o[t][j * 2 + 1]);
    }
}

// ---------------------------------------------------------------------------
// Tower head: pred[t,b] = sigmoid(th[t,b,:] . Wt2[t,:,0] + bt2[t])
// ---------------------------------------------------------------------------
__global__ __launch_bounds__(256)
void tower2_kernel(const float* __restrict__ th, const float* __restrict__ Wt2,
                   const float* __restrict__ bt2, float* __restrict__ out)
{
    const int warp = (blockIdx.x * blockDim.x + threadIdx.x) >> 5;
    const int lane = threadIdx.x & 31;
    if (warp >= NTASK * NB) return;
    const int t = warp / NB;

    const float* row = th + (size_t)warp * NT;
    const float* w   = Wt2 + (size_t)t * NT;
    float acc = 0.f;
#pragma unroll
    for (int d = lane; d < NT; d += 32) acc = fmaf(row[d], w[d], acc);
#pragma unroll
    for (int off = 16; off > 0; off >>= 1)
        acc += __shfl_xor_sync(0xffffffffu, acc, off);
    if (lane == 0) {
        const float zv = acc + bt2[t];
        out[warp] = 1.f / (1.f + expf(-zv));
    }
}

// ---------------------------------------------------------------------------
// Launch
// ---------------------------------------------------------------------------
extern "C" void kernel_launch(void* const* d_in, const int* in_sizes, int n_in,
                              void* d_out, int out_size)
{
    const float* x   = (const float*)d_in[0];
    const float* We1 = (const float*)d_in[1];
    const float* be1 = (const float*)d_in[2];
    const float* We2 = (const float*)d_in[3];
    const float* be2 = (const float*)d_in[4];
    const float* Wg  = (const float*)d_in[5];
    const float* bg  = (const float*)d_in[6];
    const float* Wt1 = (const float*)d_in[7];
    const float* bt1 = (const float*)d_in[8];
    const float* Wt2 = (const float*)d_in[9];
    const float* bt2 = (const float*)d_in[10];
    float* out = (float*)d_out;

    __nv_bfloat16 *xb, *h1b, *eob, *tinb, *We1T, *We2T, *Wt1T;
    float *th, *gates;
    cudaGetSymbolAddress((void**)&xb,    g_xb);
    cudaGetSymbolAddress((void**)&h1b,   g_h1b);
    cudaGetSymbolAddress((void**)&eob,   g_eob);
    cudaGetSymbolAddress((void**)&tinb,  g_tinb);
    cudaGetSymbolAddress((void**)&th,    g_th);
    cudaGetSymbolAddress((void**)&gates, g_gates);
    cudaGetSymbolAddress((void**)&We1T,  g_We1T);
    cudaGetSymbolAddress((void**)&We2T,  g_We2T);
    cudaGetSymbolAddress((void**)&Wt1T,  g_Wt1T);

    cudaFuncSetAttribute(gemm_bf16_kernel<__nv_bfloat16>,
                         cudaFuncAttributeMaxDynamicSharedMemorySize, SMEM_BYTES);
    cudaFuncSetAttribute(gemm_bf16_kernel<float>,
                         cudaFuncAttributeMaxDynamicSharedMemorySize, SMEM_BYTES);
    cudaFuncSetAttribute(fused_input_kernel,
                         cudaFuncAttributeMaxDynamicSharedMemorySize, GATES_SMEM);

    // One launch: all weight transposes (bf16)
    prep_weights_kernel<<<6528, 256>>>(We1, We1T, We2, We2T, Wt1, Wt1T);

    // One launch: x->bf16 convert + gate logits + softmax
    fused_input_kernel<<<NB / 32, 256, GATES_SMEM>>>(x, Wg, bg, xb, gates);

    // Expert layer 1: h1[e] = relu(x @ We1[e] + be1[e])
    gemm_bf16_kernel<__nv_bfloat16><<<dim3(NH / TN, NB / TM, NE), 128, SMEM_BYTES>>>(
        xb, We1T, be1, h1b, ND, NH,
        0LL, (long long)NH * ND, (long long)NH, (long long)NB * NH);

    // Expert layer 2: eo[e] = relu(h1[e] @ We2[e] + be2[e])
    gemm_bf16_kernel<__nv_bfloat16><<<dim3(NH / TN, NB / TM, NE), 128, SMEM_BYTES>>>(
        h1b, We2T, be2, eob, NH, NH,
        (long long)NB * NH, (long long)NH * NH, (long long)NH, (long long)NB * NH);

    // Gated combine
    combine_kernel<<<(NB * (NH / 8)) / 256, 256>>>(eob, gates, tinb);

    // Tower layer 1: th[t] = relu(tin[t] @ Wt1[t] + bt1[t])  (fp32 out)
    gemm_bf16_kernel<float><<<dim3(NT / TN, NB / TM, NTASK), 128, SMEM_BYTES>>>(
        tinb, Wt1T, bt1, th, NH, NT,
        (long long)NB * NH, (long long)NT * NH, (long long)NT, (long long)NB * NT);

    // Tower head + sigmoid
    tower2_kernel<<<(NTASK * NB * 32) / 256, 256>>>(th, Wt2, bt2, out);
}

// round 8
// speedup vs baseline: 1.1078x; 1.0146x over previous
#include <cuda_runtime.h>
#include <cuda_bf16.h>
#include <math.h>
#include <stdint.h>

// Problem constants
#define NB 16384
#define ND 1024
#define NE 8
#define NH 512
#define NT 256
#define NTASK 3

// GEMM tiling (bf16 mma.sync m16n8k16)
#define TM 128
#define TN 128
#define BK 64
#define NSTAGE 3
#define STAGE_BYTES 16384             // 128 rows x 128 B (64 bf16)
#define OFF_B (NSTAGE * STAGE_BYTES)  // 49152
#define OFF_BIAS (2 * NSTAGE * STAGE_BYTES)
#define SMEM_BYTES (OFF_BIAS + 512)   // 98816 -> 2 CTAs/SM

// Fused gates kernel smem: 24 rows x 1032 floats (pitch pads banks)
#define WG_PITCH 1032
#define GATES_SMEM (NTASK * NE * WG_PITCH * 4)

// ---------------------------------------------------------------------------
// Scratch (device globals; no runtime allocation allowed)
// ---------------------------------------------------------------------------
__device__ __nv_bfloat16 g_xb[(size_t)NB * ND];            // x in bf16
__device__ __nv_bfloat16 g_h1b[(size_t)NE * NB * NH];      // [E,B,H] bf16
__device__ __nv_bfloat16 g_eob[(size_t)NE * NB * NH];      // [E,B,H] bf16
__device__ __nv_bfloat16 g_tinb[(size_t)NTASK * NB * NH];  // [T,B,H] bf16
__device__ float g_th[(size_t)NTASK * NB * NT];            // [T,B,T] fp32
__device__ float g_gates[(size_t)NTASK * NB * NE];         // [T,B,E]
__device__ __nv_bfloat16 g_We1T[(size_t)NE * NH * ND];     // [E,H,D] bf16 NK
__device__ __nv_bfloat16 g_We2T[(size_t)NE * NH * NH];     // [E,H,H]
__device__ __nv_bfloat16 g_Wt1T[(size_t)NTASK * NT * NH];  // [T,NT,H]

// ---------------------------------------------------------------------------
// Helpers (sm_80-class PTX only)
// ---------------------------------------------------------------------------
__device__ __forceinline__ uint32_t smem_u32(const void* p) {
    uint32_t a;
    asm("{ .reg .u64 t; cvta.to.shared.u64 t, %1; cvt.u32.u64 %0, t; }" : "=r"(a) : "l"(p));
    return a;
}

#define CP_ASYNC16(dst, src) \
    asm volatile("cp.async.cg.shared.global [%0], [%1], 16;" :: "r"(dst), "l"(src))
#define CP_COMMIT() asm volatile("cp.async.commit_group;" ::: "memory")
#define CP_WAIT1()  asm volatile("cp.async.wait_group 1;" ::: "memory")
#define CP_WAIT0()  asm volatile("cp.async.wait_group 0;" ::: "memory")

__device__ __forceinline__ void ldmatrix_x4(uint32_t& r0, uint32_t& r1,
                                            uint32_t& r2, uint32_t& r3, uint32_t addr) {
    asm volatile("ldmatrix.sync.aligned.m8n8.x4.shared.b16 {%0,%1,%2,%3}, [%4];"
                 : "=r"(r0), "=r"(r1), "=r"(r2), "=r"(r3) : "r"(addr));
}

__device__ __forceinline__ void mma_bf16(float (&d)[4], const uint32_t (&a)[4],
                                         const uint32_t (&b)[2]) {
    asm volatile(
        "mma.sync.aligned.m16n8k16.row.col.f32.bf16.bf16.f32 "
        "{%0,%1,%2,%3}, {%4,%5,%6,%7}, {%8,%9}, {%0,%1,%2,%3};"
        : "+f"(d[0]), "+f"(d[1]), "+f"(d[2]), "+f"(d[3])
        : "r"(a[0]), "r"(a[1]), "r"(a[2]), "r"(a[3]), "r"(b[0]), "r"(b[1]));
}

__device__ __forceinline__ uint32_t sw128(uint32_t off) {
    return off ^ ((off >> 3) & 0x70);
}

// ---------------------------------------------------------------------------
// Merged weight transpose + bf16 convert: fp32 [z][K][N] -> bf16 [z][N][K]
// ---------------------------------------------------------------------------
__global__ __launch_bounds__(256)
void prep_weights_kernel(const float* __restrict__ We1, __nv_bfloat16* __restrict__ We1T,
                         const float* __restrict__ We2, __nv_bfloat16* __restrict__ We2T,
                         const float* __restrict__ Wt1, __nv_bfloat16* __restrict__ Wt1T)
{
    __shared__ float t[32][33];
    const int bid = blockIdx.x;

    const float* in;
    __nv_bfloat16* out;
    int K, N, z, ky, nx;
    if (bid < 4096) {                    // We1: z=8, K=1024, N=512
        const int r = bid;
        z = r >> 9; const int tt = r & 511;
        ky = tt >> 4; nx = tt & 15;
        K = ND; N = NH; in = We1; out = We1T;
    } else if (bid < 6144) {             // We2: z=8, K=512, N=512
        const int r = bid - 4096;
        z = r >> 8; const int tt = r & 255;
        ky = tt >> 4; nx = tt & 15;
        K = NH; N = NH; in = We2; out = We2T;
    } else {                             // Wt1: z=3, K=512, N=256
        const int r = bid - 6144;
        z = r >> 7; const int tt = r & 127;
        ky = tt >> 3; nx = tt & 7;
        K = NH; N = NT; in = Wt1; out = Wt1T;
    }
    in  += (size_t)z * K * N;
    out += (size_t)z * K * N;
    const int k0 = ky * 32, n0 = nx * 32;
    const int tx = threadIdx.x & 31, ty = threadIdx.x >> 5;
#pragma unroll
    for (int i = 0; i < 32; i += 8)
        t[ty + i][tx] = in[(size_t)(k0 + ty + i) * N + n0 + tx];
    __syncthreads();
#pragma unroll
    for (int i = 0; i < 32; i += 8)
        out[(size_t)(n0 + ty + i) * K + k0 + tx] = __float2bfloat16_rn(t[tx][ty + i]);
}

// ---------------------------------------------------------------------------
// Fused input kernel: x read once; writes xb (bf16) + gate softmax.
// ---------------------------------------------------------------------------
__global__ __launch_bounds__(256)
void fused_input_kernel(const float* __restrict__ x, const float* __restrict__ Wg,
                        const float* __restrict__ bg,
                        __nv_bfloat16* __restrict__ xb, float* __restrict__ gates)
{
    extern __shared__ float wg_s[];   // [24][WG_PITCH]
    const int tid = threadIdx.x;

    for (int i = tid; i < NTASK * ND * NE / 4; i += 256) {
        const float4 v = ((const float4*)Wg)[i];
        const int base = i * 4;
        const int tt = base / (ND * NE);
        const int r  = base - tt * (ND * NE);
        const int d  = r >> 3;
        const int e0 = r & 7;
        wg_s[(tt * NE + e0 + 0) * WG_PITCH + d] = v.x;
        wg_s[(tt * NE + e0 + 1) * WG_PITCH + d] = v.y;
        wg_s[(tt * NE + e0 + 2) * WG_PITCH + d] = v.z;
        wg_s[(tt * NE + e0 + 3) * WG_PITCH + d] = v.w;
    }
    __syncthreads();

    const int wid = tid >> 5, lane = tid & 31;
#pragma unroll 1
    for (int rb = 0; rb < 4; rb++) {
        const int b = blockIdx.x * 32 + wid * 4 + rb;
        const float4* xr = (const float4*)(x + (size_t)b * ND);
        __nv_bfloat162* xo = (__nv_bfloat162*)(g_xb + (size_t)b * ND);
        float acc[24];
#pragma unroll
        for (int te = 0; te < 24; te++) acc[te] = 0.f;
#pragma unroll
        for (int i = 0; i < 8; i++) {
            const int d4 = lane + 32 * i;
            const float4 xv = xr[d4];
            xo[d4 * 2 + 0] = __floats2bfloat162_rn(xv.x, xv.y);
            xo[d4 * 2 + 1] = __floats2bfloat162_rn(xv.z, xv.w);
#pragma unroll
            for (int te = 0; te < 24; te++) {
                const float4 wv = *(const float4*)(wg_s + te * WG_PITCH + d4 * 4);
                acc[te] += xv.x * wv.x + xv.y * wv.y + xv.z * wv.z + xv.w * wv.w;
            }
        }
#pragma unroll
        for (int off = 16; off > 0; off >>= 1)
#pragma unroll
            for (int te = 0; te < 24; te++)
                acc[te] += __shfl_xor_sync(0xffffffffu, acc[te], off);
        if (lane < NTASK) {
            const int t = lane;
            float v[NE];
            float mx = -1e30f;
#pragma unroll
            for (int e = 0; e < NE; e++) {
                v[e] = acc[t * NE + e] + bg[t * NE + e];
                mx = fmaxf(mx, v[e]);
            }
            float s = 0.f;
#pragma unroll
            for (int e = 0; e < NE; e++) { v[e] = expf(v[e] - mx); s += v[e]; }
            const float inv = 1.f / s;
            float* gout = gates + ((size_t)t * NB + b) * NE;
#pragma unroll
            for (int e = 0; e < NE; e++) gout[e] = v[e] * inv;
        }
    }
}

// ---------------------------------------------------------------------------
// bf16 tensor-core batched GEMM with register-fragment double buffering.
// CTA tile 128x128, BK=64, 3-stage cp.async, 4 warps (2M x 2N),
// warp tile 64x64. 2 CTAs/SM.
// ---------------------------------------------------------------------------
template <typename OutT>
__global__ __launch_bounds__(128, 2)
void gemm_bf16_kernel(const __nv_bfloat16* __restrict__ Ab,
                      const __nv_bfloat16* __restrict__ Bb,
                      const float* __restrict__ biasb, OutT* __restrict__ Cb,
                      int K, int ldc,
                      long long sA, long long sB, long long sBias, long long sC)
{
    extern __shared__ char dynsmem[];
    const uint32_t smb = smem_u32(dynsmem);

    const int z = blockIdx.z;
    const __nv_bfloat16* A  = Ab + (size_t)z * sA + (size_t)(blockIdx.y * TM) * K;
    const __nv_bfloat16* Bt = Bb + (size_t)z * sB + (size_t)(blockIdx.x * TN) * K;
    const float* bias = biasb + (size_t)z * sBias + blockIdx.x * TN;
    OutT* C = Cb + (size_t)z * sC + (size_t)(blockIdx.y * TM) * ldc + blockIdx.x * TN;

    const int tid   = threadIdx.x;
    const int wid   = tid >> 5;
    const int lane  = tid & 31;
    const int gid   = lane >> 2;
    const int tig   = lane & 3;
    const int warpM = wid >> 1;
    const int warpN = wid & 1;

    float* bias_s = (float*)(dynsmem + OFF_BIAS);
    if (tid < TN) bias_s[tid] = bias[tid];

    auto load_stage = [&](int buf, int k0) {
        const __nv_bfloat16* Ag = A + k0;
        const __nv_bfloat16* Bg = Bt + k0;
#pragma unroll
        for (int i = 0; i < 8; i++) {
            const int idx = tid + i * 128;
            const int row = idx >> 3;
            const int c8  = idx & 7;
            const uint32_t off = sw128((uint32_t)(row * 128 + c8 * 16));
            CP_ASYNC16(smb + buf * STAGE_BYTES + off, Ag + (size_t)row * K + c8 * 8);
            CP_ASYNC16(smb + OFF_B + buf * STAGE_BYTES + off, Bg + (size_t)row * K + c8 * 8);
        }
        CP_COMMIT();
    };

    float acc[4][8][4];
#pragma unroll
    for (int mt = 0; mt < 4; mt++)
#pragma unroll
        for (int nt = 0; nt < 8; nt++)
#pragma unroll
            for (int r = 0; r < 4; r++) acc[mt][nt][r] = 0.f;

    // ldmatrix lane address components
    const int a_row  = warpM * 64 + (lane & 15);
    const int a_koff = (lane >> 4) * 16;
    const int b_row  = warpN * 64 + (lane & 7) + ((lane >> 4) << 3);
    const int b_koff = ((lane >> 3) & 1) * 16;

    // Double-buffered register fragments
    uint32_t af[2][4][4];
    uint32_t bf[2][8][2];

    const int ns = K / BK;
    load_stage(0, 0);
    load_stage(1, BK);

    for (int s = 0; s < ns; s++) {
        if (s + 1 < ns) CP_WAIT1(); else CP_WAIT0();
        __syncthreads();   // single barrier per stage (fences (s+2)%3 reuse too)

        const int buf = s % NSTAGE;
        const uint32_t sa = smb + buf * STAGE_BYTES;
        const uint32_t sb = smb + OFF_B + buf * STAGE_BYTES;

        // prologue: fragments for kk=0 into buffer 0
#pragma unroll
        for (int mt = 0; mt < 4; mt++) {
            const uint32_t off = (uint32_t)((a_row + mt * 16) * 128 + a_koff);
            ldmatrix_x4(af[0][mt][0], af[0][mt][1], af[0][mt][2], af[0][mt][3],
                        sa + sw128(off));
        }
#pragma unroll
        for (int pr = 0; pr < 4; pr++) {
            const uint32_t off = (uint32_t)((b_row + pr * 16) * 128 + b_koff);
            ldmatrix_x4(bf[0][pr * 2][0], bf[0][pr * 2][1],
                        bf[0][pr * 2 + 1][0], bf[0][pr * 2 + 1][1], sb + sw128(off));
        }

#pragma unroll
        for (int kk = 0; kk < 4; kk++) {
            const int cur = kk & 1;
            const int nxt = cur ^ 1;
            if (kk < 3) {
                // prefetch fragments for kk+1 while MMAs below fill the pipe
#pragma unroll
                for (int mt = 0; mt < 4; mt++) {
                    const uint32_t off =
                        (uint32_t)((a_row + mt * 16) * 128 + (kk + 1) * 32 + a_koff);
                    ldmatrix_x4(af[nxt][mt][0], af[nxt][mt][1], af[nxt][mt][2],
                                af[nxt][mt][3], sa + sw128(off));
                }
#pragma unroll
                for (int pr = 0; pr < 4; pr++) {
                    const uint32_t off =
                        (uint32_t)((b_row + pr * 16) * 128 + (kk + 1) * 32 + b_koff);
                    ldmatrix_x4(bf[nxt][pr * 2][0], bf[nxt][pr * 2][1],
                                bf[nxt][pr * 2 + 1][0], bf[nxt][pr * 2 + 1][1],
                                sb + sw128(off));
                }
            }
#pragma unroll
            for (int mt = 0; mt < 4; mt++)
#pragma unroll
                for (int nt = 0; nt < 8; nt++)
                    mma_bf16(acc[mt][nt], af[cur][mt], bf[cur][nt]);
        }
        if (s + 2 < ns) load_stage((s + 2) % NSTAGE, (s + 2) * BK);
    }

    // Epilogue: bias + relu
#pragma unroll
    for (int mt = 0; mt < 4; mt++) {
        const int r0 = warpM * 64 + mt * 16 + gid;
#pragma unroll
        for (int nt = 0; nt < 8; nt++) {
            const int c = warpN * 64 + nt * 8 + tig * 2;
            const float2 bv = *(const float2*)(bias_s + c);
            float v0 = fmaxf(acc[mt][nt][0] + bv.x, 0.f);
            float v1 = fmaxf(acc[mt][nt][1] + bv.y, 0.f);
            float v2 = fmaxf(acc[mt][nt][2] + bv.x, 0.f);
            float v3 = fmaxf(acc[mt][nt][3] + bv.y, 0.f);
            if (sizeof(OutT) == 2) {
                *(__nv_bfloat162*)((__nv_bfloat16*)C + (size_t)r0 * ldc + c) =
                    __floats2bfloat162_rn(v0, v1);
                *(__nv_bfloat162*)((__nv_bfloat16*)C + (size_t)(r0 + 8) * ldc + c) =
                    __floats2bfloat162_rn(v2, v3);
            } else {
                *(float2*)((float*)C + (size_t)r0 * ldc + c) = make_float2(v0, v1);
                *(float2*)((float*)C + (size_t)(r0 + 8) * ldc + c) = make_float2(v2, v3);
            }
        }
    }
}

// ---------------------------------------------------------------------------
// Combine: tin[t,b,h] = sum_e gates[t,b,e] * eo[e,b,h]  (bf16 in/out)
// ---------------------------------------------------------------------------
__global__ __launch_bounds__(256)
void combine_kernel(const __nv_bfloat16* __restrict__ eo, const float* __restrict__ gates,
                    __nv_bfloat16* __restrict__ tin)
{
    const int idx = blockIdx.x * 256 + threadIdx.x;
    const int h8 = idx & (NH / 8 - 1);
    const int b  = idx >> 6;
    if (b >= NB) return;

    float g[NTASK][NE];
#pragma unroll
    for (int t = 0; t < NTASK; t++) {
        const float* gp = gates + ((size_t)t * NB + b) * NE;
#pragma unroll
        for (int e = 0; e < NE; e++) g[t][e] = gp[e];
    }

    float o[NTASK][8];
#pragma unroll
    for (int t = 0; t < NTASK; t++)
#pragma unroll
        for (int j = 0; j < 8; j++) o[t][j] = 0.f;

#pragma unroll
    for (int e = 0; e < NE; e++) {
        const __nv_bfloat162* v =
            (const __nv_bfloat162*)(eo + ((size_t)e * NB + b) * NH + h8 * 8);
        float2 f[4];
#pragma unroll
        for (int j = 0; j < 4; j++) f[j] = __bfloat1622float2(v[j]);
#pragma unroll
        for (int t = 0; t < NTASK; t++) {
            const float ge = g[t][e];
#pragma unroll
            for (int j = 0; j < 4; j++) {
                o[t][j * 2 + 0] = fmaf(ge, f[j].x, o[t][j * 2 + 0]);
                o[t][j * 2 + 1] = fmaf(ge, f[j].y, o[t][j * 2 + 1]);
            }
        }
    }
#pragma unroll
    for (int t = 0; t < NTASK; t++) {
        __nv_bfloat162* op = (__nv_bfloat162*)(tin + ((size_t)t * NB + b) * NH + h8 * 8);
#pragma unroll
        for (int j = 0; j < 4; j++)
            op[j] = __floats2bfloat162_rn(o[t][j * 2], o[t][j * 2 + 1]);
    }
}

// ---------------------------------------------------------------------------
// Tower head: pred[t,b] = sigmoid(th[t,b,:] . Wt2[t,:,0] + bt2[t])
// ---------------------------------------------------------------------------
__global__ __launch_bounds__(256)
void tower2_kernel(const float* __restrict__ th, const float* __restrict__ Wt2,
                   const float* __restrict__ bt2, float* __restrict__ out)
{
    const int warp = (blockIdx.x * blockDim.x + threadIdx.x) >> 5;
    const int lane = threadIdx.x & 31;
    if (warp >= NTASK * NB) return;
    const int t = warp / NB;

    const float* row = th + (size_t)warp * NT;
    const float* w   = Wt2 + (size_t)t * NT;
    float acc = 0.f;
#pragma unroll
    for (int d = lane; d < NT; d += 32) acc = fmaf(row[d], w[d], acc);
#pragma unroll
    for (int off = 16; off > 0; off >>= 1)
        acc += __shfl_xor_sync(0xffffffffu, acc, off);
    if (lane == 0) {
        const float zv = acc + bt2[t];
        out[warp] = 1.f / (1.f + expf(-zv));
    }
}

// ---------------------------------------------------------------------------
// Launch
// ---------------------------------------------------------------------------
extern "C" void kernel_launch(void* const* d_in, const int* in_sizes, int n_in,
                              void* d_out, int out_size)
{
    const float* x   = (const float*)d_in[0];
    const float* We1 = (const float*)d_in[1];
    const float* be1 = (const float*)d_in[2];
    const float* We2 = (const float*)d_in[3];
    const float* be2 = (const float*)d_in[4];
    const float* Wg  = (const float*)d_in[5];
    const float* bg  = (const float*)d_in[6];
    const float* Wt1 = (const float*)d_in[7];
    const float* bt1 = (const float*)d_in[8];
    const float* Wt2 = (const float*)d_in[9];
    const float* bt2 = (const float*)d_in[10];
    float* out = (float*)d_out;

    __nv_bfloat16 *xb, *h1b, *eob, *tinb, *We1T, *We2T, *Wt1T;
    float *th, *gates;
    cudaGetSymbolAddress((void**)&xb,    g_xb);
    cudaGetSymbolAddress((void**)&h1b,   g_h1b);
    cudaGetSymbolAddress((void**)&eob,   g_eob);
    cudaGetSymbolAddress((void**)&tinb,  g_tinb);
    cudaGetSymbolAddress((void**)&th,    g_th);
    cudaGetSymbolAddress((void**)&gates, g_gates);
    cudaGetSymbolAddress((void**)&We1T,  g_We1T);
    cudaGetSymbolAddress((void**)&We2T,  g_We2T);
    cudaGetSymbolAddress((void**)&Wt1T,  g_Wt1T);

    cudaFuncSetAttribute(gemm_bf16_kernel<__nv_bfloat16>,
                         cudaFuncAttributeMaxDynamicSharedMemorySize, SMEM_BYTES);
    cudaFuncSetAttribute(gemm_bf16_kernel<float>,
                         cudaFuncAttributeMaxDynamicSharedMemorySize, SMEM_BYTES);
    cudaFuncSetAttribute(fused_input_kernel,
                         cudaFuncAttributeMaxDynamicSharedMemorySize, GATES_SMEM);

    // One launch: all weight transposes (bf16)
    prep_weights_kernel<<<6528, 256>>>(We1, We1T, We2, We2T, Wt1, Wt1T);

    // One launch: x->bf16 convert + gate logits + softmax
    fused_input_kernel<<<NB / 32, 256, GATES_SMEM>>>(x, Wg, bg, xb, gates);

    // Expert layer 1: h1[e] = relu(x @ We1[e] + be1[e])
    gemm_bf16_kernel<__nv_bfloat16><<<dim3(NH / TN, NB / TM, NE), 128, SMEM_BYTES>>>(
        xb, We1T, be1, h1b, ND, NH,
        0LL, (long long)NH * ND, (long long)NH, (long long)NB * NH);

    // Expert layer 2: eo[e] = relu(h1[e] @ We2[e] + be2[e])
    gemm_bf16_kernel<__nv_bfloat16><<<dim3(NH / TN, NB / TM, NE), 128, SMEM_BYTES>>>(
        h1b, We2T, be2, eob, NH, NH,
        (long long)NB * NH, (long long)NH * NH, (long long)NH, (long long)NB * NH);

    // Gated combine
    combine_kernel<<<(NB * (NH / 8)) / 256, 256>>>(eob, gates, tinb);

    // Tower layer 1: th[t] = relu(tin[t] @ Wt1[t] + bt1[t])  (fp32 out)
    gemm_bf16_kernel<float><<<dim3(NT / TN, NB / TM, NTASK), 128, SMEM_BYTES>>>(
        tinb, Wt1T, bt1, th, NH, NT,
        (long long)NB * NH, (long long)NT * NH, (long long)NT, (long long)NB * NT);

    // Tower head + sigmoid
    tower2_kernel<<<(NTASK * NB * 32) / 256, 256>>>(th, Wt2, bt2, out);
}